// round 1
// baseline (speedup 1.0000x reference)
#include <cuda_runtime.h>
#include <math.h>

#define N_TOK 768
#define D_MODEL 512
#define CZ 128
#define NH 16
#define DH 32
#define LN_EPS 1e-5f

// ---------------- scratch (static device globals; no runtime allocs) ----------------
__device__ float g_q[N_TOK * D_MODEL];
__device__ float g_k[N_TOK * D_MODEL];
__device__ float g_v[N_TOK * D_MODEL];
__device__ float g_g[N_TOK * D_MODEL];
__device__ float g_o[N_TOK * D_MODEL];
__device__ float g_logits[(size_t)NH * N_TOK * N_TOK];  // bias -> logits -> attn (in place)
__device__ float g_A[NH * CZ];
__device__ float g_SA[NH];
__device__ float g_CB[NH];

// ---------------- K0: fold LN affine into Wz ----------------
__global__ void prep_kernel(const float* __restrict__ Wz,
                            const float* __restrict__ lnw,
                            const float* __restrict__ lnb) {
    __shared__ float red[8];
    int c = threadIdx.x;  // 128 threads
    float wc = lnw[c], bc = lnb[c];
    for (int h = 0; h < NH; h++) {
        float wz = Wz[h * CZ + c];
        float a = wz * wc;
        g_A[h * CZ + c] = a;
        float sa = a, cb = wz * bc;
        for (int o = 16; o; o >>= 1) {
            sa += __shfl_down_sync(0xffffffffu, sa, o);
            cb += __shfl_down_sync(0xffffffffu, cb, o);
        }
        if ((c & 31) == 0) { red[c >> 5] = sa; red[4 + (c >> 5)] = cb; }
        __syncthreads();
        if (c == 0) {
            g_SA[h] = red[0] + red[1] + red[2] + red[3];
            g_CB[h] = red[4] + red[5] + red[6] + red[7];
        }
        __syncthreads();
    }
}

// ---------------- K1: q,k,v,g projections: C = s @ W^T (+bias for q) ----------------
// BM=BN=64, BK=16, 256 threads, 4x4 per thread
__global__ void proj_kernel(const float* __restrict__ s,
                            const float* __restrict__ Wq, const float* __restrict__ bq,
                            const float* __restrict__ Wk, const float* __restrict__ Wv,
                            const float* __restrict__ Wg) {
    __shared__ float As[16][68];  // As[k][m]
    __shared__ float Bs[16][68];  // Bs[k][n]
    int w = blockIdx.z;
    const float* W = (w == 0) ? Wq : (w == 1) ? Wk : (w == 2) ? Wv : Wg;
    float* C = (w == 0) ? g_q : (w == 1) ? g_k : (w == 2) ? g_v : g_g;
    int bm = blockIdx.y * 64, bn = blockIdx.x * 64;
    int tid = threadIdx.x;
    int tx = tid & 15, ty = tid >> 4;
    float acc[4][4] = {};
    int lr = tid >> 2;            // 0..63
    int lc = (tid & 3) * 4;       // 0,4,8,12

    for (int k0 = 0; k0 < D_MODEL; k0 += 16) {
        float4 va = *reinterpret_cast<const float4*>(&s[(bm + lr) * D_MODEL + k0 + lc]);
        float4 vb = *reinterpret_cast<const float4*>(&W[(bn + lr) * D_MODEL + k0 + lc]);
        As[lc + 0][lr] = va.x; As[lc + 1][lr] = va.y; As[lc + 2][lr] = va.z; As[lc + 3][lr] = va.w;
        Bs[lc + 0][lr] = vb.x; Bs[lc + 1][lr] = vb.y; Bs[lc + 2][lr] = vb.z; Bs[lc + 3][lr] = vb.w;
        __syncthreads();
#pragma unroll
        for (int kk = 0; kk < 16; kk++) {
            float4 a = *reinterpret_cast<float4*>(&As[kk][ty * 4]);
            float4 b = *reinterpret_cast<float4*>(&Bs[kk][tx * 4]);
            float av[4] = {a.x, a.y, a.z, a.w};
            float bv[4] = {b.x, b.y, b.z, b.w};
#pragma unroll
            for (int ii = 0; ii < 4; ii++)
#pragma unroll
                for (int jj = 0; jj < 4; jj++) acc[ii][jj] += av[ii] * bv[jj];
        }
        __syncthreads();
    }
    float4 bias4 = make_float4(0.f, 0.f, 0.f, 0.f);
    if (w == 0) bias4 = *reinterpret_cast<const float4*>(&bq[bn + tx * 4]);
#pragma unroll
    for (int ii = 0; ii < 4; ii++) {
        float4 o4 = make_float4(acc[ii][0] + bias4.x, acc[ii][1] + bias4.y,
                                acc[ii][2] + bias4.z, acc[ii][3] + bias4.w);
        *reinterpret_cast<float4*>(&C[(bm + ty * 4 + ii) * D_MODEL + bn + tx * 4]) = o4;
    }
}

// ---------------- K2: pair bias: LN(z) @ A^T via linearity trick ----------------
// block: (j-tile of 64, i). smem tile of z, per-row stats, smem GEMM.
__global__ void bias_kernel(const float* __restrict__ z) {
    __shared__ float zs[64][132];
    __shared__ float As[16][132];
    __shared__ float mu[64], rs[64];
    int i = blockIdx.y;
    int j0 = blockIdx.x * 64;
    int tid = threadIdx.x;

    for (int t = tid; t < NH * CZ; t += 256) As[t >> 7][t & 127] = g_A[t];

    const float* zb = z + ((size_t)i * N_TOK + j0) * CZ;
#pragma unroll
    for (int it = 0; it < 8; it++) {
        int f4 = tid + it * 256;      // 0..2047
        int r = f4 >> 5, c4 = f4 & 31;
        float4 v = *reinterpret_cast<const float4*>(zb + r * CZ + c4 * 4);
        *reinterpret_cast<float4*>(&zs[r][c4 * 4]) = v;
    }
    __syncthreads();

    if (tid < 64) {
        float sm = 0.f, sq = 0.f;
#pragma unroll 8
        for (int c4 = 0; c4 < 32; c4++) {
            float4 v = *reinterpret_cast<float4*>(&zs[tid][c4 * 4]);
            sm += v.x + v.y + v.z + v.w;
            sq += v.x * v.x + v.y * v.y + v.z * v.z + v.w * v.w;
        }
        float m = sm * (1.0f / CZ);
        float var = sq * (1.0f / CZ) - m * m;
        mu[tid] = m;
        rs[tid] = rsqrtf(var + LN_EPS);
    }
    __syncthreads();

    int lane = tid & 31;
    int h0 = (tid >> 5) * 2;  // 8 groups x 2 heads
    float a00 = 0.f, a01 = 0.f, a10 = 0.f, a11 = 0.f;
#pragma unroll 8
    for (int c4 = 0; c4 < 32; c4++) {
        float4 z0 = *reinterpret_cast<float4*>(&zs[lane][c4 * 4]);
        float4 z1 = *reinterpret_cast<float4*>(&zs[lane + 32][c4 * 4]);
        float4 p0 = *reinterpret_cast<float4*>(&As[h0][c4 * 4]);
        float4 p1 = *reinterpret_cast<float4*>(&As[h0 + 1][c4 * 4]);
        a00 += z0.x * p0.x + z0.y * p0.y + z0.z * p0.z + z0.w * p0.w;
        a01 += z1.x * p0.x + z1.y * p0.y + z1.z * p0.z + z1.w * p0.w;
        a10 += z0.x * p1.x + z0.y * p1.y + z0.z * p1.z + z0.w * p1.w;
        a11 += z1.x * p1.x + z1.y * p1.y + z1.z * p1.z + z1.w * p1.w;
    }
    float m0 = mu[lane], r0 = rs[lane];
    float m1 = mu[lane + 32], r1 = rs[lane + 32];
    {
        float sa = g_SA[h0], cb = g_CB[h0];
        size_t base = ((size_t)h0 * N_TOK + i) * N_TOK + j0;
        g_logits[base + lane] = r0 * (a00 - m0 * sa) + cb;
        g_logits[base + lane + 32] = r1 * (a01 - m1 * sa) + cb;
    }
    {
        float sa = g_SA[h0 + 1], cb = g_CB[h0 + 1];
        size_t base = ((size_t)(h0 + 1) * N_TOK + i) * N_TOK + j0;
        g_logits[base + lane] = r0 * (a10 - m0 * sa) + cb;
        g_logits[base + lane + 32] = r1 * (a11 - m1 * sa) + cb;
    }
}

// ---------------- K3a: logits += scale * Q K^T ----------------
// block: (jt 64, it 32, h)
__global__ void logits_kernel() {
    __shared__ float Qs[32][36];
    __shared__ float Ks[64][36];
    int h = blockIdx.z;
    int i0 = blockIdx.y * 32;
    int j0 = blockIdx.x * 64;
    int tid = threadIdx.x;
    {
        int r = tid >> 3, c4 = tid & 7;
        float4 v = *reinterpret_cast<const float4*>(&g_q[(i0 + r) * D_MODEL + h * DH + c4 * 4]);
        *reinterpret_cast<float4*>(&Qs[r][c4 * 4]) = v;
    }
#pragma unroll
    for (int it = 0; it < 2; it++) {
        int f4 = tid + it * 256;
        int r = f4 >> 3, c4 = f4 & 7;
        float4 v = *reinterpret_cast<const float4*>(&g_k[(j0 + r) * D_MODEL + h * DH + c4 * 4]);
        *reinterpret_cast<float4*>(&Ks[r][c4 * 4]) = v;
    }
    __syncthreads();
    int tx = tid & 15, ty = tid >> 4;
    float acc[2][4] = {};
#pragma unroll
    for (int d4 = 0; d4 < 8; d4++) {
        float4 q0 = *reinterpret_cast<float4*>(&Qs[ty * 2][d4 * 4]);
        float4 q1 = *reinterpret_cast<float4*>(&Qs[ty * 2 + 1][d4 * 4]);
#pragma unroll
        for (int m = 0; m < 4; m++) {
            float4 kv = *reinterpret_cast<float4*>(&Ks[tx + 16 * m][d4 * 4]);
            acc[0][m] += q0.x * kv.x + q0.y * kv.y + q0.z * kv.z + q0.w * kv.w;
            acc[1][m] += q1.x * kv.x + q1.y * kv.y + q1.z * kv.z + q1.w * kv.w;
        }
    }
    const float scale = 0.17677669529663687f;  // 32^-0.5
#pragma unroll
    for (int ii = 0; ii < 2; ii++)
#pragma unroll
        for (int m = 0; m < 4; m++) {
            size_t idx = ((size_t)h * N_TOK + i0 + ty * 2 + ii) * N_TOK + j0 + tx + 16 * m;
            g_logits[idx] = g_logits[idx] + acc[ii][m] * scale;
        }
}

// ---------------- K3b: row softmax ----------------
__global__ void softmax_kernel() {
    __shared__ float red[8];
    int i = blockIdx.x, h = blockIdx.y;
    float* row = &g_logits[((size_t)h * N_TOK + i) * N_TOK];
    int tid = threadIdx.x;
    float v0 = row[tid], v1 = row[tid + 256], v2 = row[tid + 512];
    float mx = fmaxf(v0, fmaxf(v1, v2));
    for (int o = 16; o; o >>= 1) mx = fmaxf(mx, __shfl_xor_sync(0xffffffffu, mx, o));
    if ((tid & 31) == 0) red[tid >> 5] = mx;
    __syncthreads();
    float m = red[0];
#pragma unroll
    for (int t = 1; t < 8; t++) m = fmaxf(m, red[t]);
    v0 = __expf(v0 - m); v1 = __expf(v1 - m); v2 = __expf(v2 - m);
    float sm = v0 + v1 + v2;
    for (int o = 16; o; o >>= 1) sm += __shfl_xor_sync(0xffffffffu, sm, o);
    __syncthreads();
    if ((tid & 31) == 0) red[tid >> 5] = sm;
    __syncthreads();
    float s = red[0];
#pragma unroll
    for (int t = 1; t < 8; t++) s += red[t];
    float inv = 1.0f / s;
    row[tid] = v0 * inv; row[tid + 256] = v1 * inv; row[tid + 512] = v2 * inv;
}

// ---------------- K3c: O = P @ V ----------------
// block: (it 64, h); loop j tiles of 64
__global__ void attnv_kernel() {
    __shared__ float Ps[64][68];
    __shared__ float Vs[32][68];  // transposed: Vs[d][j]
    int h = blockIdx.y;
    int i0 = blockIdx.x * 64;
    int tid = threadIdx.x;
    int tx = tid & 15, ty = tid >> 4;
    float acc[4][2] = {};
    for (int j0 = 0; j0 < N_TOK; j0 += 64) {
#pragma unroll
        for (int it = 0; it < 4; it++) {
            int f4 = tid + it * 256;
            int r = f4 >> 4, c4 = f4 & 15;
            float4 v = *reinterpret_cast<const float4*>(
                &g_logits[((size_t)h * N_TOK + i0 + r) * N_TOK + j0 + c4 * 4]);
            *reinterpret_cast<float4*>(&Ps[r][c4 * 4]) = v;
        }
#pragma unroll
        for (int it = 0; it < 8; it++) {
            int e = tid + it * 256;
            int r = e >> 5, d = e & 31;
            Vs[d][r] = g_v[(j0 + r) * D_MODEL + h * DH + d];
        }
        __syncthreads();
#pragma unroll 8
        for (int j4 = 0; j4 < 16; j4++) {
            float4 va = *reinterpret_cast<float4*>(&Vs[tx][j4 * 4]);
            float4 vb = *reinterpret_cast<float4*>(&Vs[tx + 16][j4 * 4]);
#pragma unroll
            for (int m = 0; m < 4; m++) {
                float4 p = *reinterpret_cast<float4*>(&Ps[ty + 16 * m][j4 * 4]);
                acc[m][0] += p.x * va.x + p.y * va.y + p.z * va.z + p.w * va.w;
                acc[m][1] += p.x * vb.x + p.y * vb.y + p.z * vb.z + p.w * vb.w;
            }
        }
        __syncthreads();
    }
#pragma unroll
    for (int m = 0; m < 4; m++) {
        g_o[(i0 + ty + 16 * m) * D_MODEL + h * DH + tx] = acc[m][0];
        g_o[(i0 + ty + 16 * m) * D_MODEL + h * DH + tx + 16] = acc[m][1];
    }
}

// ---------------- K4: out = (o * sigmoid(g)) @ Wo^T ----------------
__global__ void out_kernel(const float* __restrict__ Wo, float* __restrict__ out) {
    __shared__ float As[16][68];
    __shared__ float Bs[16][68];
    int bm = blockIdx.y * 64, bn = blockIdx.x * 64;
    int tid = threadIdx.x;
    int tx = tid & 15, ty = tid >> 4;
    float acc[4][4] = {};
    int lr = tid >> 2;
    int lc = (tid & 3) * 4;

    for (int k0 = 0; k0 < D_MODEL; k0 += 16) {
        float4 va = *reinterpret_cast<const float4*>(&g_o[(bm + lr) * D_MODEL + k0 + lc]);
        float4 vg = *reinterpret_cast<const float4*>(&g_g[(bm + lr) * D_MODEL + k0 + lc]);
        float4 vb = *reinterpret_cast<const float4*>(&Wo[(bn + lr) * D_MODEL + k0 + lc]);
        va.x *= 1.0f / (1.0f + __expf(-vg.x));
        va.y *= 1.0f / (1.0f + __expf(-vg.y));
        va.z *= 1.0f / (1.0f + __expf(-vg.z));
        va.w *= 1.0f / (1.0f + __expf(-vg.w));
        As[lc + 0][lr] = va.x; As[lc + 1][lr] = va.y; As[lc + 2][lr] = va.z; As[lc + 3][lr] = va.w;
        Bs[lc + 0][lr] = vb.x; Bs[lc + 1][lr] = vb.y; Bs[lc + 2][lr] = vb.z; Bs[lc + 3][lr] = vb.w;
        __syncthreads();
#pragma unroll
        for (int kk = 0; kk < 16; kk++) {
            float4 a = *reinterpret_cast<float4*>(&As[kk][ty * 4]);
            float4 b = *reinterpret_cast<float4*>(&Bs[kk][tx * 4]);
            float av[4] = {a.x, a.y, a.z, a.w};
            float bv[4] = {b.x, b.y, b.z, b.w};
#pragma unroll
            for (int ii = 0; ii < 4; ii++)
#pragma unroll
                for (int jj = 0; jj < 4; jj++) acc[ii][jj] += av[ii] * bv[jj];
        }
        __syncthreads();
    }
#pragma unroll
    for (int ii = 0; ii < 4; ii++) {
        float4 o4 = make_float4(acc[ii][0], acc[ii][1], acc[ii][2], acc[ii][3]);
        *reinterpret_cast<float4*>(&out[(bm + ty * 4 + ii) * D_MODEL + bn + tx * 4]) = o4;
    }
}

// ---------------- launch ----------------
extern "C" void kernel_launch(void* const* d_in, const int* in_sizes, int n_in,
                              void* d_out, int out_size) {
    const float* s   = (const float*)d_in[0];
    const float* z   = (const float*)d_in[1];
    const float* Wq  = (const float*)d_in[2];
    const float* bq  = (const float*)d_in[3];
    const float* Wk  = (const float*)d_in[4];
    const float* Wv  = (const float*)d_in[5];
    const float* Wg  = (const float*)d_in[6];
    const float* Wo  = (const float*)d_in[7];
    const float* lnw = (const float*)d_in[8];
    const float* lnb = (const float*)d_in[9];
    const float* Wz  = (const float*)d_in[10];
    float* out = (float*)d_out;

    prep_kernel<<<1, 128>>>(Wz, lnw, lnb);
    proj_kernel<<<dim3(D_MODEL / 64, N_TOK / 64, 4), 256>>>(s, Wq, bq, Wk, Wv, Wg);
    bias_kernel<<<dim3(N_TOK / 64, N_TOK), 256>>>(z);
    logits_kernel<<<dim3(N_TOK / 64, N_TOK / 32, NH), 256>>>();
    softmax_kernel<<<dim3(N_TOK, NH), 256>>>();
    attnv_kernel<<<dim3(N_TOK / 64, NH), 256>>>();
    out_kernel<<<dim3(D_MODEL / 64, N_TOK / 64), 256>>>(Wo, out);
}